// round 16
// baseline (speedup 1.0000x reference)
#include <cuda_runtime.h>
#include <cstdint>

#define B_  8
#define N_  2048
#define D_  1024
#define E_  64
#define CAP_ 64
#define TOK_ (B_*N_)                     // 16384
#define DTOT_ ((long long)TOK_*E_*CAP_)  // 67108864
#define SLICES 4
#define KS_ (D_/SLICES)                  // 256 K per slice

// -------- scratch (device globals; no allocation allowed) --------
__device__ float d_part[SLICES][TOK_][E_];   // 16MB split-K partial logits
__device__ float d_g1[TOK_], d_g2[TOK_];
__device__ int   d_i1[TOK_], d_i2[TOK_];
__device__ int   d_keep2[TOK_];
__device__ float d_sumg[B_*E_];
__device__ int   d_cnt1[B_*E_];

// -------- fork/join stream + events (host objects, created pre-main) -------
struct HxStreams {
    cudaStream_t s2;
    cudaEvent_t  evF, evJ;
    HxStreams() {
        cudaStreamCreateWithFlags(&s2, cudaStreamNonBlocking);
        cudaEventCreateWithFlags(&evF, cudaEventDisableTiming);
        cudaEventCreateWithFlags(&evJ, cudaEventDisableTiming);
    }
};
static HxStreams hx;

// -------- packed f32x2 helpers --------
__device__ __forceinline__ unsigned long long pk2(float v) {
    unsigned long long r;
    asm("mov.b64 %0, {%1, %1};" : "=l"(r) : "f"(v));
    return r;
}
__device__ __forceinline__ void fma2(unsigned long long& acc, unsigned long long a,
                                     unsigned long long b) {
    asm("fma.rn.f32x2 %0, %1, %2, %0;" : "+l"(acc) : "l"(a), "l"(b));
}
__device__ __forceinline__ void unpk2(unsigned long long v, float& lo, float& hi) {
    asm("mov.b64 {%0, %1}, %2;" : "=f"(lo), "=f"(hi) : "l"(v));
}
// streaming (evict-first) 16B zero store
__device__ __forceinline__ void stcs_zero16(float* p) {
    asm volatile("st.global.cs.v4.f32 [%0], {%1, %1, %1, %1};"
                 :: "l"(p), "f"(0.0f) : "memory");
}
// cp.async 16B global->shared
__device__ __forceinline__ void cpa16(uint32_t dst, const void* src) {
    asm volatile("cp.async.cg.shared.global [%0], [%1], 16;"
                 :: "r"(dst), "l"(src) : "memory");
}

// -------- per-token top2 + softmax + gate output (group of 4 lanes) --------
__device__ __forceinline__ void do_token(float v[16], int g, int b, int tok,
                                         float ls[16]) {
    float m1 = -1e30f, m2 = -1e30f; int i1 = 0, i2 = 0;
#pragma unroll
    for (int j = 0; j < 16; j++) {
        int e = (g << 2) + ((j >> 2) << 4) + (j & 3);
        float val = v[j];
        if (val > m1)      { m2 = m1; i2 = i1; m1 = val; i1 = e; }
        else if (val > m2) { m2 = val; i2 = e; }
    }
#pragma unroll
    for (int d = 1; d <= 2; d <<= 1) {
        float om1 = __shfl_xor_sync(0xffffffffu, m1, d);
        int   oi1 = __shfl_xor_sync(0xffffffffu, i1, d);
        float om2 = __shfl_xor_sync(0xffffffffu, m2, d);
        int   oi2 = __shfl_xor_sync(0xffffffffu, i2, d);
        if (om1 > m1 || (om1 == m1 && oi1 < i1)) {
            float c = m1; int ci = i1;
            m1 = om1; i1 = oi1;
            if (om2 > c || (om2 == c && oi2 < ci)) { m2 = om2; i2 = oi2; }
            else                                   { m2 = c;   i2 = ci;  }
        } else {
            if (om1 > m2 || (om1 == m2 && oi1 < i2)) { m2 = om1; i2 = oi1; }
        }
    }
    float s = 0.0f;
#pragma unroll
    for (int j = 0; j < 16; j++) { v[j] = __expf(v[j] - m1); s += v[j]; }
    s += __shfl_xor_sync(0xffffffffu, s, 1);
    s += __shfl_xor_sync(0xffffffffu, s, 2);
    float invZ = 1.0f / s;
#pragma unroll
    for (int j = 0; j < 16; j++) ls[j] += v[j] * invZ;

    if (g == 0) {
        float e2v = __expf(m2 - m1);
        float den = 1.0f + e2v + 1e-9f * s;
        float g1 = 1.0f / den, g2 = e2v / den;
        d_g1[tok] = g1;  d_g2[tok] = g2;
        d_i1[tok] = i1;  d_i2[tok] = i2;
        d_keep2[tok] = (g2 > 0.2f) ? 1 : 0;
        atomicAdd(&d_cnt1[(b << 6) + i1], 1);
    }
}

// -------- K1a: split-K GEMM, cp.async double-buffered ----------------------
#define TPB1 128
#define KC2  32
#define NCH  (KS_/KC2)   // 8 chunks per slice
#define TOKB 64
__global__ __launch_bounds__(TPB1, 7) void k1a_gemm(const float* __restrict__ x,
                                                    const float* __restrict__ W,
                                                    int slice_base) {
    __shared__ float sx[2][TOKB * KC2];   // 2 x 8KB, 16B-swizzled rows
    __shared__ float sw[2][KC2 * E_];     // 2 x 8KB

    const int tid   = threadIdx.x;
    const int g     = tid & 3;           // expert group: experts g*4 + 16i + s
    const int p     = tid >> 2;          // token pair id 0..31
    const int psel  = p & 7;             // swizzle selector for rows 2p,2p+1
    const int tok0  = blockIdx.x * TOKB;
    const int tokA  = tok0 + 2*p;
    const int tokB  = tokA + 1;
    const int slice = slice_base + blockIdx.y;
    const int kbase = slice * KS_;

    const uint32_t sx0 = (uint32_t)__cvta_generic_to_shared(&sx[0][0]);
    const uint32_t sw0 = (uint32_t)__cvta_generic_to_shared(&sw[0][0]);

    unsigned long long accA[8], accB[8];
#pragma unroll
    for (int j = 0; j < 8; j++) { accA[j] = 0ULL; accB[j] = 0ULL; }

    auto load_chunk = [&](int c, int buf) {
        const int kc = kbase + c * KC2;
        const uint32_t wd = sw0 + (uint32_t)buf * 8192;
#pragma unroll
        for (int j = 0; j < 4; j++) {
            int idx = tid + j * TPB1;
            cpa16(wd + idx * 16, W + (size_t)kc * E_ + idx * 4);
        }
        const uint32_t xd = sx0 + (uint32_t)buf * 8192;
#pragma unroll
        for (int j = 0; j < 4; j++) {
            int idx = tid + j * TPB1;
            int r   = idx >> 3;             // row 0..63
            int cc  = idx & 7;              // 16B chunk in row
            int scc = cc ^ ((r >> 1) & 7);  // swizzle
            cpa16(xd + (r * KC2 + scc * 4) * 4,
                  x + (size_t)(tok0 + r) * D_ + kc + cc * 4);
        }
        asm volatile("cp.async.commit_group;" ::: "memory");
    };

    load_chunk(0, 0);

#pragma unroll 1
    for (int c = 0; c < NCH; c++) {
        const int buf = c & 1;
        if (c + 1 < NCH) {
            load_chunk(c + 1, buf ^ 1);
            asm volatile("cp.async.wait_group 1;" ::: "memory");
        } else {
            asm volatile("cp.async.wait_group 0;" ::: "memory");
        }
        __syncthreads();

        const float* xrowA = &sx[buf][2 * p * KC2];
        const float* xrowB = xrowA + KC2;
        const float* wrow  = &sw[buf][g * 4];
#pragma unroll
        for (int kk = 0; kk < KC2; kk++) {
            int a = (((kk >> 2) ^ psel) << 2) + (kk & 3);   // de-swizzled col
            unsigned long long xpA = pk2(xrowA[a]);
            unsigned long long xpB = pk2(xrowB[a]);
            const ulonglong2* wp = (const ulonglong2*)(wrow + kk * E_);
            ulonglong2 w0 = wp[0];
            ulonglong2 w1 = wp[4];
            ulonglong2 w2 = wp[8];
            ulonglong2 w3 = wp[12];
            fma2(accA[0], xpA, w0.x); fma2(accA[1], xpA, w0.y);
            fma2(accA[2], xpA, w1.x); fma2(accA[3], xpA, w1.y);
            fma2(accA[4], xpA, w2.x); fma2(accA[5], xpA, w2.y);
            fma2(accA[6], xpA, w3.x); fma2(accA[7], xpA, w3.y);
            fma2(accB[0], xpB, w0.x); fma2(accB[1], xpB, w0.y);
            fma2(accB[2], xpB, w1.x); fma2(accB[3], xpB, w1.y);
            fma2(accB[4], xpB, w2.x); fma2(accB[5], xpB, w2.y);
            fma2(accB[6], xpB, w3.x); fma2(accB[7], xpB, w3.y);
        }
        __syncthreads();
    }

    {
        ulonglong2* pA = (ulonglong2*)&d_part[slice][tokA][g*16];
        ulonglong2* pB = (ulonglong2*)&d_part[slice][tokB][g*16];
        pA[0] = make_ulonglong2(accA[0], accA[1]);
        pA[1] = make_ulonglong2(accA[2], accA[3]);
        pA[2] = make_ulonglong2(accA[4], accA[5]);
        pA[3] = make_ulonglong2(accA[6], accA[7]);
        pB[0] = make_ulonglong2(accB[0], accB[1]);
        pB[1] = make_ulonglong2(accB[2], accB[3]);
        pB[2] = make_ulonglong2(accB[4], accB[5]);
        pB[3] = make_ulonglong2(accB[6], accB[7]);
    }
}

// -------- K1b: sum slices + softmax/top2/gates/loss (1 token / 4 lanes) ----
__global__ __launch_bounds__(TPB1) void k1b_decide() {
    const int tid = threadIdx.x;
    const int g   = tid & 3;
    const int q   = tid >> 2;                 // token in block 0..31
    const int tok = blockIdx.x * 32 + q;
    const int b   = tok >> 11;

    float v[16];
    {
        const float4* p0 = (const float4*)&d_part[0][tok][g*16];
        const float4* p1 = (const float4*)&d_part[1][tok][g*16];
        const float4* p2 = (const float4*)&d_part[2][tok][g*16];
        const float4* p3 = (const float4*)&d_part[3][tok][g*16];
#pragma unroll
        for (int j = 0; j < 4; j++) {
            float4 a = p0[j], bb = p1[j], c = p2[j], d = p3[j];
            v[4*j+0] = ((a.x + bb.x) + c.x) + d.x;
            v[4*j+1] = ((a.y + bb.y) + c.y) + d.y;
            v[4*j+2] = ((a.z + bb.z) + c.z) + d.z;
            v[4*j+3] = ((a.w + bb.w) + c.w) + d.w;
        }
    }

    float ls[16];
#pragma unroll
    for (int j = 0; j < 16; j++) ls[j] = 0.0f;

    do_token(v, g, b, tok, ls);

#pragma unroll
    for (int j = 0; j < 16; j++) {
        float t = ls[j];
        t += __shfl_xor_sync(0xffffffffu, t, 4);
        t += __shfl_xor_sync(0xffffffffu, t, 8);
        t += __shfl_xor_sync(0xffffffffu, t, 16);
        if ((tid & 31) < 4) {
            int e = (g << 2) + ((j >> 2) << 4) + (j & 3);
            atomicAdd(&d_sumg[(b << 6) + e], t);
        }
    }
}

// -------- K3a: pure zero-fill, 256-thr blocks (R10 proven overlap partner) -
__global__ __launch_bounds__(256) void k3a_fill(float* __restrict__ out) {
    const int gwarp = (blockIdx.x * blockDim.x + threadIdx.x) >> 5;  // = token
    const int lane  = threadIdx.x & 31;

    const long long baseD = (long long)gwarp * (E_ * CAP_);
    float* pd = out + baseD;           // dispatch plane (4096 floats)
    float* pc = out + DTOT_ + baseD;   // combine plane
#pragma unroll
    for (int i = 0; i < 32; i++) {
        stcs_zero16(pd + 4*(lane + i*32));
        stcs_zero16(pc + 4*(lane + i*32));
    }
}

// -------- K2: scan (prefetched) + DIRECT scatter, 512 threads --------------
#define NW2 16
__global__ __launch_bounds__(512) void k2_scan_scatter(float* __restrict__ out,
                                                       long long out_size) {
    const int b    = blockIdx.x;
    const int tid  = threadIdx.x;
    const int w    = tid >> 5;           // warp 0..15
    const int lane = tid & 31;
    const unsigned lt = (1u << lane) - 1u;

    __shared__ int cnt[NW2][E_];
    __shared__ int pre[NW2][E_];
    __shared__ int m1c[E_];

    const int base = b * N_ + w * 128;   // each warp: 4 chunks of 32 tokens

    // ---- upfront batched prefetch: independent LDGs, one latency wait ----
    int i1v[4], i2v[4], kp2[4];
    float g1v[4], g2v[4];
#pragma unroll
    for (int c = 0; c < 4; c++) i1v[c] = d_i1[base + c*32 + lane];
#pragma unroll
    for (int c = 0; c < 4; c++) i2v[c] = d_i2[base + c*32 + lane];
#pragma unroll
    for (int c = 0; c < 4; c++) kp2[c] = d_keep2[base + c*32 + lane];
#pragma unroll
    for (int c = 0; c < 4; c++) g1v[c] = d_g1[base + c*32 + lane];
#pragma unroll
    for (int c = 0; c < 4; c++) g2v[c] = d_g2[base + c*32 + lane];

    for (int i = tid; i < NW2*E_; i += 512) ((int*)cnt)[i] = 0;
    __syncthreads();

    // ---- pass 1: top-1 (registers + smem only) ----
    int lp1[4];
#pragma unroll
    for (int c = 0; c < 4; c++) {
        int i1 = i1v[c];
        unsigned grp = __match_any_sync(0xffffffffu, i1);
        int before = __popc(grp & lt);
        int cv = cnt[w][i1];
        __syncwarp();
        lp1[c] = cv + before;
        if (lane == __ffs(grp) - 1) cnt[w][i1] = cv + __popc(grp);
        __syncwarp();
    }
    __syncthreads();

    if (tid < E_) {
        int s = 0;
#pragma unroll
        for (int ww = 0; ww < NW2; ww++) { pre[ww][tid] = s; s += cnt[ww][tid]; }
        m1c[tid] = min(s, CAP_);
    }
    __syncthreads();

    // direct scatter of top-1 entries (fill has already joined)
#pragma unroll
    for (int c = 0; c < 4; c++) {
        int t   = base + c*32 + lane;
        int pos = lp1[c] + pre[w][i1v[c]];
        if (pos < CAP_) {
            long long baseD = (long long)t * (E_*CAP_);
            int o = i1v[c]*CAP_ + pos;
            out[baseD + o]         = 1.0f;
            out[DTOT_ + baseD + o] = g1v[c];
        }
    }
    __syncthreads();

    // ---- pass 2: top-2 (thresholded), offset by mask_1_count ----
    for (int i = tid; i < NW2*E_; i += 512) ((int*)cnt)[i] = 0;
    __syncthreads();

    int lp2[4];
#pragma unroll
    for (int c = 0; c < 4; c++) {
        int i2 = i2v[c];
        int kp = kp2[c];
        unsigned km  = __ballot_sync(0xffffffffu, kp);
        unsigned grp = __match_any_sync(0xffffffffu, i2) & km;
        int before = __popc(grp & lt);
        int cv = cnt[w][i2];
        __syncwarp();
        lp2[c] = cv + before;
        if (kp && lane == __ffs(grp) - 1) cnt[w][i2] = cv + __popc(grp);
        __syncwarp();
    }
    __syncthreads();

    if (tid < E_) {
        int s = 0;
#pragma unroll
        for (int ww = 0; ww < NW2; ww++) { pre[ww][tid] = s; s += cnt[ww][tid]; }
    }
    __syncthreads();

#pragma unroll
    for (int c = 0; c < 4; c++) {
        if (!kp2[c]) continue;
        int t   = base + c*32 + lane;
        int e   = i2v[c];
        int pos = lp2[c] + pre[w][e] + m1c[e];
        if (pos < CAP_) {
            long long baseD = (long long)t * (E_*CAP_);
            int o = e*CAP_ + pos;
            out[baseD + o]         = 1.0f;
            out[DTOT_ + baseD + o] = g2v[c];
        }
    }

    // ---- block 0: loss finalize + scratch re-zero for next graph replay ----
    if (b == 0) {
        __shared__ float red[16];
        const int i = tid;   // 512 threads cover 512 entries
        float v = d_sumg[i] * (float)d_cnt1[i];
        v += __shfl_xor_sync(0xffffffffu, v, 16);
        v += __shfl_xor_sync(0xffffffffu, v, 8);
        v += __shfl_xor_sync(0xffffffffu, v, 4);
        v += __shfl_xor_sync(0xffffffffu, v, 2);
        v += __shfl_xor_sync(0xffffffffu, v, 1);
        if ((i & 31) == 0) red[i >> 5] = v;
        d_sumg[i] = 0.0f;  d_cnt1[i] = 0;
        __syncthreads();
        if (i == 0) {
            float s = 0.0f;
            for (int ww = 0; ww < 16; ww++) s += red[ww];
            float loss = s * (8.0f / ((float)N_ * (float)N_));
            if (out_size > 2*DTOT_) out[2*DTOT_] = loss;
        }
    }
}

extern "C" void kernel_launch(void* const* d_in, const int* in_sizes, int n_in,
                              void* d_out, int out_size) {
    const float* x = (const float*)d_in[0];
    const float* W = (const float*)d_in[1];
    float* out = (float*)d_out;

    // fork; k1a split into 2 half-machine launches so fill blocks co-reside
    cudaEventRecord(hx.evF, 0);
    cudaStreamWaitEvent(hx.s2, hx.evF, 0);

    dim3 gHalf(TOK_/TOKB, 2);                            // 512 blocks each
    k1a_gemm<<<gHalf, TPB1>>>(x, W, 0);                  // slices 0-1
    k3a_fill<<<TOK_*32/256, 256, 0, hx.s2>>>(out);       // forked stream
    k1a_gemm<<<gHalf, TPB1>>>(x, W, 2);                  // slices 2-3
    k1b_decide<<<TOK_/32, TPB1>>>();                     // main stream

    // join: scan+scatter needs the fill completed (it writes into out)
    cudaEventRecord(hx.evJ, hx.s2);
    cudaStreamWaitEvent(0, hx.evJ, 0);
    k2_scan_scatter<<<B_, 512>>>(out, (long long)out_size);
}

// round 17
// speedup vs baseline: 1.0309x; 1.0309x over previous
#include <cuda_runtime.h>
#include <cstdint>

#define B_  8
#define N_  2048
#define D_  1024
#define E_  64
#define CAP_ 64
#define TOK_ (B_*N_)                     // 16384
#define DTOT_ ((long long)TOK_*E_*CAP_)  // 67108864
#define SLICES 4
#define KS_ (D_/SLICES)                  // 256 K per slice

// -------- scratch (device globals; no allocation allowed) --------
__device__ float d_part[SLICES][TOK_][E_];   // 16MB split-K partial logits
__device__ float d_g1[TOK_], d_g2[TOK_];
__device__ int   d_i1[TOK_], d_i2[TOK_];
__device__ int   d_pos1[TOK_], d_pos2[TOK_];
__device__ int   d_keep1[TOK_], d_keep2[TOK_];
__device__ float d_sumg[B_*E_];
__device__ int   d_cnt1[B_*E_];

// -------- fork/join stream + events (host objects, created pre-main) -------
struct HxStreams {
    cudaStream_t s2;
    cudaEvent_t  evF, evJ;
    HxStreams() {
        cudaStreamCreateWithFlags(&s2, cudaStreamNonBlocking);
        cudaEventCreateWithFlags(&evF, cudaEventDisableTiming);
        cudaEventCreateWithFlags(&evJ, cudaEventDisableTiming);
    }
};
static HxStreams hx;

// -------- packed f32x2 helpers --------
__device__ __forceinline__ unsigned long long pk2(float v) {
    unsigned long long r;
    asm("mov.b64 %0, {%1, %1};" : "=l"(r) : "f"(v));
    return r;
}
__device__ __forceinline__ void fma2(unsigned long long& acc, unsigned long long a,
                                     unsigned long long b) {
    asm("fma.rn.f32x2 %0, %1, %2, %0;" : "+l"(acc) : "l"(a), "l"(b));
}
__device__ __forceinline__ void unpk2(unsigned long long v, float& lo, float& hi) {
    asm("mov.b64 {%0, %1}, %2;" : "=f"(lo), "=f"(hi) : "l"(v));
}
// streaming (evict-first) 16B zero store
__device__ __forceinline__ void stcs_zero16(float* p) {
    asm volatile("st.global.cs.v4.f32 [%0], {%1, %1, %1, %1};"
                 :: "l"(p), "f"(0.0f) : "memory");
}
// cp.async 16B global->shared
__device__ __forceinline__ void cpa16(uint32_t dst, const void* src) {
    asm volatile("cp.async.cg.shared.global [%0], [%1], 16;"
                 :: "r"(dst), "l"(src) : "memory");
}

// -------- per-token top2 + softmax + gate output (group of 4 lanes) --------
__device__ __forceinline__ void do_token(float v[16], int g, int b, int tok,
                                         float ls[16]) {
    float m1 = -1e30f, m2 = -1e30f; int i1 = 0, i2 = 0;
#pragma unroll
    for (int j = 0; j < 16; j++) {
        int e = (g << 2) + ((j >> 2) << 4) + (j & 3);
        float val = v[j];
        if (val > m1)      { m2 = m1; i2 = i1; m1 = val; i1 = e; }
        else if (val > m2) { m2 = val; i2 = e; }
    }
#pragma unroll
    for (int d = 1; d <= 2; d <<= 1) {
        float om1 = __shfl_xor_sync(0xffffffffu, m1, d);
        int   oi1 = __shfl_xor_sync(0xffffffffu, i1, d);
        float om2 = __shfl_xor_sync(0xffffffffu, m2, d);
        int   oi2 = __shfl_xor_sync(0xffffffffu, i2, d);
        if (om1 > m1 || (om1 == m1 && oi1 < i1)) {
            float c = m1; int ci = i1;
            m1 = om1; i1 = oi1;
            if (om2 > c || (om2 == c && oi2 < ci)) { m2 = om2; i2 = oi2; }
            else                                   { m2 = c;   i2 = ci;  }
        } else {
            if (om1 > m2 || (om1 == m2 && oi1 < i2)) { m2 = om1; i2 = oi1; }
        }
    }
    float s = 0.0f;
#pragma unroll
    for (int j = 0; j < 16; j++) { v[j] = __expf(v[j] - m1); s += v[j]; }
    s += __shfl_xor_sync(0xffffffffu, s, 1);
    s += __shfl_xor_sync(0xffffffffu, s, 2);
    float invZ = 1.0f / s;
#pragma unroll
    for (int j = 0; j < 16; j++) ls[j] += v[j] * invZ;

    if (g == 0) {
        float e2v = __expf(m2 - m1);
        float den = 1.0f + e2v + 1e-9f * s;
        float g1 = 1.0f / den, g2 = e2v / den;
        d_g1[tok] = g1;  d_g2[tok] = g2;
        d_i1[tok] = i1;  d_i2[tok] = i2;
        d_keep2[tok] = (g2 > 0.2f) ? 1 : 0;
        atomicAdd(&d_cnt1[(b << 6) + i1], 1);
    }
}

// -------- K1a: split-K GEMM, cp.async double-buffered (R15 proven) ---------
#define TPB1 128
#define KC2  32
#define NCH  (KS_/KC2)   // 8 chunks per slice
#define TOKB 64
__global__ __launch_bounds__(TPB1, 7) void k1a_gemm(const float* __restrict__ x,
                                                    const float* __restrict__ W) {
    __shared__ float sx[2][TOKB * KC2];   // 2 x 8KB, 16B-swizzled rows
    __shared__ float sw[2][KC2 * E_];     // 2 x 8KB

    const int tid   = threadIdx.x;
    const int g     = tid & 3;           // expert group: experts g*4 + 16i + s
    const int p     = tid >> 2;          // token pair id 0..31
    const int psel  = p & 7;             // swizzle selector for rows 2p,2p+1
    const int tok0  = blockIdx.x * TOKB;
    const int tokA  = tok0 + 2*p;
    const int tokB  = tokA + 1;
    const int slice = blockIdx.y;
    const int kbase = slice * KS_;

    const uint32_t sx0 = (uint32_t)__cvta_generic_to_shared(&sx[0][0]);
    const uint32_t sw0 = (uint32_t)__cvta_generic_to_shared(&sw[0][0]);

    unsigned long long accA[8], accB[8];
#pragma unroll
    for (int j = 0; j < 8; j++) { accA[j] = 0ULL; accB[j] = 0ULL; }

    auto load_chunk = [&](int c, int buf) {
        const int kc = kbase + c * KC2;
        const uint32_t wd = sw0 + (uint32_t)buf * 8192;
#pragma unroll
        for (int j = 0; j < 4; j++) {
            int idx = tid + j * TPB1;
            cpa16(wd + idx * 16, W + (size_t)kc * E_ + idx * 4);
        }
        const uint32_t xd = sx0 + (uint32_t)buf * 8192;
#pragma unroll
        for (int j = 0; j < 4; j++) {
            int idx = tid + j * TPB1;
            int r   = idx >> 3;             // row 0..63
            int cc  = idx & 7;              // 16B chunk in row
            int scc = cc ^ ((r >> 1) & 7);  // swizzle
            cpa16(xd + (r * KC2 + scc * 4) * 4,
                  x + (size_t)(tok0 + r) * D_ + kc + cc * 4);
        }
        asm volatile("cp.async.commit_group;" ::: "memory");
    };

    load_chunk(0, 0);

#pragma unroll 1
    for (int c = 0; c < NCH; c++) {
        const int buf = c & 1;
        if (c + 1 < NCH) {
            load_chunk(c + 1, buf ^ 1);
            asm volatile("cp.async.wait_group 1;" ::: "memory");
        } else {
            asm volatile("cp.async.wait_group 0;" ::: "memory");
        }
        __syncthreads();

        const float* xrowA = &sx[buf][2 * p * KC2];
        const float* xrowB = xrowA + KC2;
        const float* wrow  = &sw[buf][g * 4];
#pragma unroll
        for (int kk = 0; kk < KC2; kk++) {
            int a = (((kk >> 2) ^ psel) << 2) + (kk & 3);   // de-swizzled col
            unsigned long long xpA = pk2(xrowA[a]);
            unsigned long long xpB = pk2(xrowB[a]);
            const ulonglong2* wp = (const ulonglong2*)(wrow + kk * E_);
            ulonglong2 w0 = wp[0];
            ulonglong2 w1 = wp[4];
            ulonglong2 w2 = wp[8];
            ulonglong2 w3 = wp[12];
            fma2(accA[0], xpA, w0.x); fma2(accA[1], xpA, w0.y);
            fma2(accA[2], xpA, w1.x); fma2(accA[3], xpA, w1.y);
            fma2(accA[4], xpA, w2.x); fma2(accA[5], xpA, w2.y);
            fma2(accA[6], xpA, w3.x); fma2(accA[7], xpA, w3.y);
            fma2(accB[0], xpB, w0.x); fma2(accB[1], xpB, w0.y);
            fma2(accB[2], xpB, w1.x); fma2(accB[3], xpB, w1.y);
            fma2(accB[4], xpB, w2.x); fma2(accB[5], xpB, w2.y);
            fma2(accB[6], xpB, w3.x); fma2(accB[7], xpB, w3.y);
        }
        __syncthreads();
    }

    {
        ulonglong2* pA = (ulonglong2*)&d_part[slice][tokA][g*16];
        ulonglong2* pB = (ulonglong2*)&d_part[slice][tokB][g*16];
        pA[0] = make_ulonglong2(accA[0], accA[1]);
        pA[1] = make_ulonglong2(accA[2], accA[3]);
        pA[2] = make_ulonglong2(accA[4], accA[5]);
        pA[3] = make_ulonglong2(accA[6], accA[7]);
        pB[0] = make_ulonglong2(accB[0], accB[1]);
        pB[1] = make_ulonglong2(accB[2], accB[3]);
        pB[2] = make_ulonglong2(accB[4], accB[5]);
        pB[3] = make_ulonglong2(accB[6], accB[7]);
    }
}

// -------- K1b: sum slices + softmax/top2/gates/loss (1 token / 4 lanes) ----
__global__ __launch_bounds__(TPB1) void k1b_decide() {
    const int tid = threadIdx.x;
    const int g   = tid & 3;
    const int q   = tid >> 2;                 // token in block 0..31
    const int tok = blockIdx.x * 32 + q;
    const int b   = tok >> 11;

    float v[16];
    {
        const float4* p0 = (const float4*)&d_part[0][tok][g*16];
        const float4* p1 = (const float4*)&d_part[1][tok][g*16];
        const float4* p2 = (const float4*)&d_part[2][tok][g*16];
        const float4* p3 = (const float4*)&d_part[3][tok][g*16];
#pragma unroll
        for (int j = 0; j < 4; j++) {
            float4 a = p0[j], bb = p1[j], c = p2[j], d = p3[j];
            v[4*j+0] = ((a.x + bb.x) + c.x) + d.x;
            v[4*j+1] = ((a.y + bb.y) + c.y) + d.y;
            v[4*j+2] = ((a.z + bb.z) + c.z) + d.z;
            v[4*j+3] = ((a.w + bb.w) + c.w) + d.w;
        }
    }

    float ls[16];
#pragma unroll
    for (int j = 0; j < 16; j++) ls[j] = 0.0f;

    do_token(v, g, b, tok, ls);

#pragma unroll
    for (int j = 0; j < 16; j++) {
        float t = ls[j];
        t += __shfl_xor_sync(0xffffffffu, t, 4);
        t += __shfl_xor_sync(0xffffffffu, t, 8);
        t += __shfl_xor_sync(0xffffffffu, t, 16);
        if ((tid & 31) < 4) {
            int e = (g << 2) + ((j >> 2) << 4) + (j & 3);
            atomicAdd(&d_sumg[(b << 6) + e], t);
        }
    }
}

// -------- K3a: pure zero-fill, 256-thr blocks (R10/R15 proven) -------------
__global__ __launch_bounds__(256) void k3a_fill(float* __restrict__ out) {
    const int gwarp = (blockIdx.x * blockDim.x + threadIdx.x) >> 5;  // = token
    const int lane  = threadIdx.x & 31;

    const long long baseD = (long long)gwarp * (E_ * CAP_);
    float* pd = out + baseD;           // dispatch plane (4096 floats)
    float* pc = out + DTOT_ + baseD;   // combine plane
#pragma unroll
    for (int i = 0; i < 32; i++) {
        stcs_zero16(pd + 4*(lane + i*32));
        stcs_zero16(pc + 4*(lane + i*32));
    }
}

// -------- K2: scan only (pre-join; no out writes) — 512 threads ------------
#define NW2 16
__global__ __launch_bounds__(512) void k2_scan() {
    const int b    = blockIdx.x;
    const int tid  = threadIdx.x;
    const int w    = tid >> 5;           // warp 0..15
    const int lane = tid & 31;
    const unsigned lt = (1u << lane) - 1u;

    __shared__ int cnt[NW2][E_];
    __shared__ int pre[NW2][E_];
    __shared__ int m1c[E_];

    const int base = b * N_ + w * 128;   // each warp: 4 chunks of 32 tokens

    int i1v[4], i2v[4], kp2[4];
#pragma unroll
    for (int c = 0; c < 4; c++) i1v[c] = d_i1[base + c*32 + lane];
#pragma unroll
    for (int c = 0; c < 4; c++) i2v[c] = d_i2[base + c*32 + lane];
#pragma unroll
    for (int c = 0; c < 4; c++) kp2[c] = d_keep2[base + c*32 + lane];

    for (int i = tid; i < NW2*E_; i += 512) ((int*)cnt)[i] = 0;
    __syncthreads();

    // ---- pass 1: top-1 ----
    int lp1[4];
#pragma unroll
    for (int c = 0; c < 4; c++) {
        int i1 = i1v[c];
        unsigned grp = __match_any_sync(0xffffffffu, i1);
        int before = __popc(grp & lt);
        int cv = cnt[w][i1];
        __syncwarp();
        lp1[c] = cv + before;
        if (lane == __ffs(grp) - 1) cnt[w][i1] = cv + __popc(grp);
        __syncwarp();
    }
    __syncthreads();

    if (tid < E_) {
        int s = 0;
#pragma unroll
        for (int ww = 0; ww < NW2; ww++) { pre[ww][tid] = s; s += cnt[ww][tid]; }
        m1c[tid] = min(s, CAP_);
    }
    __syncthreads();

#pragma unroll
    for (int c = 0; c < 4; c++) {
        int t   = base + c*32 + lane;
        int pos = lp1[c] + pre[w][i1v[c]];
        d_pos1[t]  = pos;
        d_keep1[t] = (pos < CAP_) ? 1 : 0;
    }
    __syncthreads();

    // ---- pass 2: top-2 (thresholded), offset by mask_1_count ----
    for (int i = tid; i < NW2*E_; i += 512) ((int*)cnt)[i] = 0;
    __syncthreads();

    int lp2[4];
#pragma unroll
    for (int c = 0; c < 4; c++) {
        int i2 = i2v[c];
        int kp = kp2[c];
        unsigned km  = __ballot_sync(0xffffffffu, kp);
        unsigned grp = __match_any_sync(0xffffffffu, i2) & km;
        int before = __popc(grp & lt);
        int cv = cnt[w][i2];
        __syncwarp();
        lp2[c] = cv + before;
        if (kp && lane == __ffs(grp) - 1) cnt[w][i2] = cv + __popc(grp);
        __syncwarp();
    }
    __syncthreads();

    if (tid < E_) {
        int s = 0;
#pragma unroll
        for (int ww = 0; ww < NW2; ww++) { pre[ww][tid] = s; s += cnt[ww][tid]; }
    }
    __syncthreads();

#pragma unroll
    for (int c = 0; c < 4; c++) {
        int t = base + c*32 + lane;
        if (kp2[c]) {
            int e   = i2v[c];
            int pos = lp2[c] + pre[w][e] + m1c[e];
            d_pos2[t]  = pos;
            d_keep2[t] = (pos < CAP_) ? 1 : 0;
        } else {
            d_keep2[t] = 0;
        }
    }
}

// -------- K3b: tiny scatter + loss finalize (post-join) --------------------
__global__ __launch_bounds__(256) void k3b_scatter(float* __restrict__ out,
                                                   long long out_size) {
    const int tok = blockIdx.x * blockDim.x + threadIdx.x;   // 16384 threads
    const long long baseD = (long long)tok * (E_ * CAP_);
    if (d_keep1[tok]) {
        int t = d_i1[tok]*CAP_ + d_pos1[tok];
        out[baseD + t]         = 1.0f;
        out[DTOT_ + baseD + t] = d_g1[tok];
    }
    if (d_keep2[tok]) {
        int t = d_i2[tok]*CAP_ + d_pos2[tok];
        out[baseD + t]         = 1.0f;
        out[DTOT_ + baseD + t] = d_g2[tok];
    }

    // ---- block 0: loss finalize + scratch re-zero for next graph replay ----
    if (blockIdx.x == 0) {
        __shared__ float red[8];
        const int i = threadIdx.x;   // 256 threads cover 512 entries
        float v = d_sumg[i]       * (float)d_cnt1[i]
                + d_sumg[i + 256] * (float)d_cnt1[i + 256];
        v += __shfl_xor_sync(0xffffffffu, v, 16);
        v += __shfl_xor_sync(0xffffffffu, v, 8);
        v += __shfl_xor_sync(0xffffffffu, v, 4);
        v += __shfl_xor_sync(0xffffffffu, v, 2);
        v += __shfl_xor_sync(0xffffffffu, v, 1);
        if ((i & 31) == 0) red[i >> 5] = v;
        d_sumg[i] = 0.0f;       d_cnt1[i] = 0;
        d_sumg[i + 256] = 0.0f; d_cnt1[i + 256] = 0;
        __syncthreads();
        if (i == 0) {
            float s = 0.0f;
            for (int w = 0; w < 8; w++) s += red[w];
            float loss = s * (8.0f / ((float)N_ * (float)N_));
            if (out_size > 2*DTOT_) out[2*DTOT_] = loss;
        }
    }
}

extern "C" void kernel_launch(void* const* d_in, const int* in_sizes, int n_in,
                              void* d_out, int out_size) {
    const float* x = (const float*)d_in[0];
    const float* W = (const float*)d_in[1];
    float* out = (float*)d_out;

    // R15-proven fork order: k1a first (owns SMs), fill overlaps its drain.
    cudaEventRecord(hx.evF, 0);
    cudaStreamWaitEvent(hx.s2, hx.evF, 0);

    dim3 g1a(TOK_/TOKB, SLICES);                         // 256 x 4 = 1024 blocks
    k1a_gemm<<<g1a, TPB1>>>(x, W);                       // main stream
    k3a_fill<<<TOK_*32/256, 256, 0, hx.s2>>>(out);       // forked stream
    k1b_decide<<<TOK_/32, TPB1>>>();                     // main stream
    k2_scan<<<B_, 512>>>();                              // main: under fill tail

    // join: only the tiny scatter needs the fill completed
    cudaEventRecord(hx.evJ, hx.s2);
    cudaStreamWaitEvent(0, hx.evJ, 0);
    k3b_scatter<<<TOK_/256, 256>>>(out, (long long)out_size);
}